// round 10
// baseline (speedup 1.0000x reference)
#include <cuda_runtime.h>

#define NL 8192
#define NC 16384
#define BD 256
#define DD 64
#define SLOPE 0.01f
#define LCAP 64
#define CCAP 64
#define SCAPC 40

#define OUT_L 0
#define OUT_C 2097152
#define OUT_U 6291456

#define SCAN_BLOCKS 2048
#define PREP_BLOCKS 256
#define COMB_BLOCKS 81

// ---------------- device scratch ----------------
__device__ float g_LT[(size_t)NL * BD];
__device__ float g_CnewT[(size_t)NC * BD];
__device__ int   g_litCnt[NL];
__device__ int   g_litList[(size_t)NL * LCAP];
__device__ int   g_clauseCnt[NC];
__device__ int   g_clauseList[(size_t)NC * CCAP];
__device__ float g_WC[DD * 128];   // [WCu1 | Wcm]
__device__ float g_WL[DD * 192];   // [WLu1 | Wcl | WLu3]
__device__ float g_bcm[DD];
__device__ float g_bcl[DD];
__device__ float g_sumL[BD];
__device__ float g_sumC[BD];

__device__ __forceinline__ float leaky(float x) { return x >= 0.f ? x : SLOPE * x; }

// acc[4] (packed f32x2) += {w,w} * x[0..7]   (2 LDS.128, 4 FFMA2)
#define FMA8P(acc, wf, xptr) do {                                                \
    unsigned long long _w2;                                                      \
    asm("mov.b64 %0, {%1, %1};" : "=l"(_w2) : "f"(wf));                          \
    const ulonglong2* _x = (const ulonglong2*)(xptr);                            \
    ulonglong2 _p0 = _x[0]; ulonglong2 _p1 = _x[1];                              \
    asm("fma.rn.f32x2 %0, %1, %2, %0;" : "+l"(acc[0]) : "l"(_w2), "l"(_p0.x));   \
    asm("fma.rn.f32x2 %0, %1, %2, %0;" : "+l"(acc[1]) : "l"(_w2), "l"(_p0.y));   \
    asm("fma.rn.f32x2 %0, %1, %2, %0;" : "+l"(acc[2]) : "l"(_w2), "l"(_p1.x));   \
    asm("fma.rn.f32x2 %0, %1, %2, %0;" : "+l"(acc[3]) : "l"(_w2), "l"(_p1.y));   \
} while (0)

// ---------------- kernels ----------------

__global__ void k_zero() {
    int i = blockIdx.x * blockDim.x + threadIdx.x;
    if (i < NL) g_litCnt[i] = 0;
    if (i < NC) g_clauseCnt[i] = 0;
    if (i < BD) { g_sumL[i] = 0.f; g_sumC[i] = 0.f; }
}

__device__ __forceinline__ void scan_add(int c, int l) {
    int p = atomicAdd(&g_clauseCnt[c], 1);
    if (p < CCAP) g_clauseList[(size_t)c * CCAP + p] = l;
    int q = atomicAdd(&g_litCnt[l], 1);
    if (q < LCAP) g_litList[(size_t)l * LCAP + q] = c;
}

__device__ __forceinline__ void scan_proc(uint4 v, unsigned idx) {
    if (v.x | v.y | v.z | v.w) {
        int c = idx >> 11;
        int lb = (idx & 2047) << 2;
        if (v.x) scan_add(c, lb);
        if (v.y) scan_add(c, lb + 1);
        if (v.z) scan_add(c, lb + 2);
        if (v.w) scan_add(c, lb + 3);
    }
}

// Heterogeneous: scan A | transpose L | build fused weights.
__global__ __launch_bounds__(256) void k_mega(const uint4* __restrict__ A4,
                                              const float* __restrict__ L,
                                              const float* __restrict__ WCu,
                                              const float* __restrict__ WLmsg,
                                              const float* __restrict__ bLmsg,
                                              const float* __restrict__ WLu,
                                              const float* __restrict__ WCmsg,
                                              const float* __restrict__ bCmsg) {
    int bid = blockIdx.x;
    int tid = threadIdx.x;
    if (bid < SCAN_BLOCKS) {
        const unsigned stride = SCAN_BLOCKS * 256u;
        unsigned i = bid * 256u + tid;
        #pragma unroll 1
        for (int it = 0; it < 8; it++) {
            uint4 v0 = __ldcs(&A4[i]);
            uint4 v1 = __ldcs(&A4[i + stride]);
            uint4 v2 = __ldcs(&A4[i + 2 * stride]);
            uint4 v3 = __ldcs(&A4[i + 3 * stride]);
            uint4 v4 = __ldcs(&A4[i + 4 * stride]);
            uint4 v5 = __ldcs(&A4[i + 5 * stride]);
            uint4 v6 = __ldcs(&A4[i + 6 * stride]);
            uint4 v7 = __ldcs(&A4[i + 7 * stride]);
            unsigned any = (v0.x | v0.y | v0.z | v0.w) | (v1.x | v1.y | v1.z | v1.w)
                         | (v2.x | v2.y | v2.z | v2.w) | (v3.x | v3.y | v3.z | v3.w)
                         | (v4.x | v4.y | v4.z | v4.w) | (v5.x | v5.y | v5.z | v5.w)
                         | (v6.x | v6.y | v6.z | v6.w) | (v7.x | v7.y | v7.z | v7.w);
            if (any) {
                scan_proc(v0, i);
                scan_proc(v1, i + stride);
                scan_proc(v2, i + 2 * stride);
                scan_proc(v3, i + 3 * stride);
                scan_proc(v4, i + 4 * stride);
                scan_proc(v5, i + 5 * stride);
                scan_proc(v6, i + 6 * stride);
                scan_proc(v7, i + 7 * stride);
            }
            i += stride * 8;
        }
    } else if (bid < SCAN_BLOCKS + PREP_BLOCKS) {
        __shared__ float s[256 * 33];
        int l0 = (bid - SCAN_BLOCKS) * 32;
        for (int idx = tid; idx < 256 * 32; idx += 256) {
            int r = idx >> 5, c = idx & 31;
            s[r * 33 + c] = L[(size_t)r * NL + l0 + c];
        }
        __syncthreads();
        #pragma unroll
        for (int li = 0; li < 32; li++)
            g_LT[(size_t)(l0 + li) * BD + tid] = s[tid * 33 + li];
    } else {
        int idx = (bid - SCAN_BLOCKS - PREP_BLOCKS) * 256 + tid;
        if (idx < 4096) {
            int o = idx >> 6, i = idx & 63;
            float s = 0.f;
            #pragma unroll
            for (int j = 0; j < 64; j++) s += WCu[o * 128 + 64 + j] * WLmsg[j * 64 + i];
            g_WC[o * 128 + 64 + i] = s;
        } else if (idx < 8192) {
            int k = idx - 4096;
            int o = k >> 6, i = k & 63;
            float s = 0.f;
            #pragma unroll
            for (int j = 0; j < 64; j++) s += WLu[o * 192 + 64 + j] * WCmsg[j * 64 + i];
            g_WL[o * 192 + 64 + i] = s;
        } else if (idx < 12288) {
            int k = idx - 8192;
            int o = k >> 6, i = k & 63;
            g_WC[o * 128 + i] = WCu[o * 128 + i];
        } else if (idx < 16384) {
            int k = idx - 12288;
            int o = k >> 6, i = k & 63;
            g_WL[o * 192 + i] = WLu[o * 192 + i];
        } else if (idx < 20480) {
            int k = idx - 16384;
            int o = k >> 6, i = k & 63;
            g_WL[o * 192 + 128 + i] = WLu[o * 192 + 128 + i];
        } else if (idx < 20544) {
            int o = idx - 20480;
            float s = 0.f;
            #pragma unroll
            for (int j = 0; j < 64; j++) s += WCu[o * 128 + 64 + j] * bLmsg[j];
            g_bcm[o] = s;
        } else if (idx < 20608) {
            int o = idx - 20544;
            float s = 0.f;
            #pragma unroll
            for (int j = 0; j < 64; j++) s += WLu[o * 192 + 64 + j] * bCmsg[j];
            g_bcl[o] = s;
        }
    }
}

// Clause update, 8 clauses/block (2048 blocks): gather(MLP8) + matvec.
__global__ __launch_bounds__(256) void k_clauseUp(const float* __restrict__ C,
                                                  const float* __restrict__ bCu,
                                                  float* __restrict__ outC) {
    extern __shared__ float sm[];
    float* s_ct  = sm;                     // 256*12 (8 used)
    float* s_S   = s_ct + 256 * 12;        // 256*12
    int*   s_cnt = (int*)(s_S + 256 * 12); // 8
    int*   s_list = s_cnt + 8;             // 8*SCAPC

    int tid = threadIdx.x;
    int c0 = blockIdx.x * 8;

    if (tid < 8) s_cnt[tid] = min(g_clauseCnt[c0 + tid], SCAPC);
    for (int idx = tid; idx < 256 * 8; idx += 256) {
        int r = idx >> 3, cc = idx & 7;
        s_ct[r * 12 + cc] = C[(size_t)r * NC + c0 + cc];
    }
    __syncthreads();
    for (int idx = tid; idx < 8 * SCAPC; idx += 256) {
        int cc = idx / SCAPC, i = idx - cc * SCAPC;
        if (i < s_cnt[cc]) s_list[idx] = g_clauseList[(size_t)(c0 + cc) * CCAP + i];
    }
    __syncthreads();

    // interleaved gather: MLP 8
    {
        int cnt[8], mx = 0;
        #pragma unroll
        for (int k = 0; k < 8; k++) { cnt[k] = s_cnt[k]; mx = max(mx, cnt[k]); }
        float a[8] = {0.f,0.f,0.f,0.f,0.f,0.f,0.f,0.f};
        for (int i = 0; i < mx; i++) {
            #pragma unroll
            for (int k = 0; k < 8; k++) {
                if (i < cnt[k]) {
                    int node = s_list[k * SCAPC + i];
                    a[k] += __ldg(&g_LT[(size_t)node * BD + tid]);
                }
            }
        }
        #pragma unroll
        for (int k = 0; k < 8; k++) s_S[tid * 12 + k] = a[k];
    }
    __syncthreads();

    int b = tid >> 6, ch = tid & 63;
    unsigned long long acc2[4];
    #pragma unroll
    for (int i = 0; i < 4; i++) acc2[i] = 0ull;
    const float4* wc = (const float4*)(g_WC + ch * 128);
    #pragma unroll 4
    for (int j4 = 0; j4 < 16; j4++) {
        float4 wv = __ldg(&wc[j4]);
        const float* x = s_ct + (b * 64 + j4 * 4) * 12;
        FMA8P(acc2, wv.x, x);
        FMA8P(acc2, wv.y, x + 12);
        FMA8P(acc2, wv.z, x + 24);
        FMA8P(acc2, wv.w, x + 36);
    }
    #pragma unroll 4
    for (int j4 = 16; j4 < 32; j4++) {
        float4 wv = __ldg(&wc[j4]);
        const float* x = s_S + (b * 64 + (j4 - 16) * 4) * 12;
        FMA8P(acc2, wv.x, x);
        FMA8P(acc2, wv.y, x + 12);
        FMA8P(acc2, wv.z, x + 24);
        FMA8P(acc2, wv.w, x + 36);
    }
    float acc[8];
    #pragma unroll
    for (int k = 0; k < 4; k++)
        asm("mov.b64 {%0, %1}, %2;" : "=f"(acc[2*k]), "=f"(acc[2*k+1]) : "l"(acc2[k]));

    float bb = __ldg(&bCu[ch]), bc = __ldg(&g_bcm[ch]);
    float lsum = 0.f;
    #pragma unroll
    for (int cc = 0; cc < 8; cc++) {
        float v = leaky(acc[cc] + bb + (float)s_cnt[cc] * bc);
        acc[cc] = v;
        lsum += v;
        g_CnewT[(size_t)(c0 + cc) * BD + tid] = v;
    }
    float4* orow = (float4*)(outC + (size_t)tid * NC + c0);
    orow[0] = make_float4(acc[0], acc[1], acc[2], acc[3]);
    orow[1] = make_float4(acc[4], acc[5], acc[6], acc[7]);
    atomicAdd(&g_sumC[tid], lsum);
}

// Literal update, 8 literals/block (1024 blocks): gather(MLP8) + matvec (3 terms).
__global__ __launch_bounds__(256) void k_literalUp(const float* __restrict__ bLu,
                                                   float* __restrict__ outL) {
    extern __shared__ float sm[];
    float* s_X   = sm;                     // 256*12 (L)
    float* s_Xf  = s_X + 256 * 12;         // 256*12 (L_flip)
    float* s_S   = s_Xf + 256 * 12;        // 256*12
    int*   s_cnt = (int*)(s_S + 256 * 12); // 8
    int*   s_list = s_cnt + 8;             // 8*LCAP

    int tid = threadIdx.x;
    int l0 = blockIdx.x * 8;
    int lf0 = (l0 + 4096) & (NL - 1);

    if (tid < 8) s_cnt[tid] = min(g_litCnt[l0 + tid], LCAP);
    for (int idx = tid; idx < 256 * 8; idx += 256) {
        int cc = idx >> 8, r = idx & 255;
        s_X[r * 12 + cc]  = g_LT[(size_t)(l0 + cc) * BD + r];
        s_Xf[r * 12 + cc] = g_LT[(size_t)(lf0 + cc) * BD + r];
    }
    __syncthreads();
    for (int idx = tid; idx < 8 * LCAP; idx += 256) {
        int cc = idx >> 6, i = idx & 63;
        if (i < s_cnt[cc]) s_list[idx] = g_litList[(size_t)(l0 + cc) * LCAP + i];
    }
    __syncthreads();

    {
        int cnt[8], mx = 0;
        #pragma unroll
        for (int k = 0; k < 8; k++) { cnt[k] = s_cnt[k]; mx = max(mx, cnt[k]); }
        float a[8] = {0.f,0.f,0.f,0.f,0.f,0.f,0.f,0.f};
        for (int i = 0; i < mx; i++) {
            #pragma unroll
            for (int k = 0; k < 8; k++) {
                if (i < cnt[k]) {
                    int node = s_list[k * LCAP + i];
                    a[k] += __ldg(&g_CnewT[(size_t)node * BD + tid]);
                }
            }
        }
        #pragma unroll
        for (int k = 0; k < 8; k++) s_S[tid * 12 + k] = a[k];
    }
    __syncthreads();

    int b = tid >> 6, ch = tid & 63;
    unsigned long long acc2[4];
    #pragma unroll
    for (int i = 0; i < 4; i++) acc2[i] = 0ull;
    const float4* wl = (const float4*)(g_WL + ch * 192);
    #pragma unroll 4
    for (int j4 = 0; j4 < 16; j4++) {          // term1: L
        float4 wv = __ldg(&wl[j4]);
        const float* x = s_X + (b * 64 + j4 * 4) * 12;
        FMA8P(acc2, wv.x, x);
        FMA8P(acc2, wv.y, x + 12);
        FMA8P(acc2, wv.z, x + 24);
        FMA8P(acc2, wv.w, x + 36);
    }
    #pragma unroll 4
    for (int j4 = 16; j4 < 32; j4++) {         // term2: messages
        float4 wv = __ldg(&wl[j4]);
        const float* x = s_S + (b * 64 + (j4 - 16) * 4) * 12;
        FMA8P(acc2, wv.x, x);
        FMA8P(acc2, wv.y, x + 12);
        FMA8P(acc2, wv.z, x + 24);
        FMA8P(acc2, wv.w, x + 36);
    }
    #pragma unroll 4
    for (int j4 = 32; j4 < 48; j4++) {         // term3: L_flip
        float4 wv = __ldg(&wl[j4]);
        const float* x = s_Xf + (b * 64 + (j4 - 32) * 4) * 12;
        FMA8P(acc2, wv.x, x);
        FMA8P(acc2, wv.y, x + 12);
        FMA8P(acc2, wv.z, x + 24);
        FMA8P(acc2, wv.w, x + 36);
    }
    float acc[8];
    #pragma unroll
    for (int k = 0; k < 4; k++)
        asm("mov.b64 {%0, %1}, %2;" : "=f"(acc[2*k]), "=f"(acc[2*k+1]) : "l"(acc2[k]));

    float bb = __ldg(&bLu[ch]), bc = __ldg(&g_bcl[ch]);
    float lsum = 0.f;
    #pragma unroll
    for (int cc = 0; cc < 8; cc++) {
        float v = leaky(acc[cc] + bb + (float)s_cnt[cc] * bc);
        acc[cc] = v;
        lsum += v;
    }
    float4* orow = (float4*)(outL + (size_t)tid * NL + l0);
    orow[0] = make_float4(acc[0], acc[1], acc[2], acc[3]);
    orow[1] = make_float4(acc[4], acc[5], acc[6], acc[7]);
    atomicAdd(&g_sumL[tid], lsum);
}

__global__ void k_U(const float* __restrict__ U, const float* __restrict__ WUu,
                    const float* __restrict__ bUu, float* __restrict__ out) {
    __shared__ float glb[4 * 192];
    int tid = threadIdx.x;
    int b = tid >> 6, ch = tid & 63;
    glb[b * 192 + ch]       = g_sumL[tid];
    glb[b * 192 + 64 + ch]  = g_sumC[tid];
    glb[b * 192 + 128 + ch] = U[tid];
    __syncthreads();
    float s = bUu[ch];
    #pragma unroll 8
    for (int i = 0; i < 192; i++) s += WUu[ch * 192 + i] * glb[b * 192 + i];
    out[tid] = leaky(s);
}

// ---------------- launch ----------------
extern "C" void kernel_launch(void* const* d_in, const int* in_sizes, int n_in,
                              void* d_out, int out_size) {
    const float* L     = (const float*)d_in[0];
    const float* C     = (const float*)d_in[1];
    const float* U     = (const float*)d_in[2];
    const float* A     = (const float*)d_in[3];
    const float* WLmsg = (const float*)d_in[5];
    const float* bLmsg = (const float*)d_in[6];
    const float* WCmsg = (const float*)d_in[7];
    const float* bCmsg = (const float*)d_in[8];
    const float* WLu   = (const float*)d_in[9];
    const float* bLu   = (const float*)d_in[10];
    const float* WCu   = (const float*)d_in[11];
    const float* bCu   = (const float*)d_in[12];
    const float* WUu   = (const float*)d_in[13];
    const float* bUu   = (const float*)d_in[14];
    float* out = (float*)d_out;

    const int smem_clause  = (256 * 12 * 2 + 8 + 8 * SCAPC) * 4;
    const int smem_literal = (256 * 12 * 3 + 8 + 8 * LCAP) * 4;
    cudaFuncSetAttribute(k_clauseUp,  cudaFuncAttributeMaxDynamicSharedMemorySize, smem_clause);
    cudaFuncSetAttribute(k_literalUp, cudaFuncAttributeMaxDynamicSharedMemorySize, smem_literal);

    k_zero<<<64, 256>>>();
    k_mega<<<SCAN_BLOCKS + PREP_BLOCKS + COMB_BLOCKS, 256>>>(
        (const uint4*)A, L, WCu, WLmsg, bLmsg, WLu, WCmsg, bCmsg);
    k_clauseUp<<<NC / 8, 256, smem_clause>>>(C, bCu, out + OUT_C);
    k_literalUp<<<NL / 8, 256, smem_literal>>>(bLu, out + OUT_L);
    k_U<<<1, 256>>>(U, WUu, bUu, out + OUT_U);
}

// round 11
// speedup vs baseline: 1.2715x; 1.2715x over previous
#include <cuda_runtime.h>

#define NL 8192
#define NC 16384
#define BD 256
#define DD 64
#define SLOPE 0.01f
#define LCAP 64
#define CCAP 64
#define SCAPC 40

#define OUT_L 0
#define OUT_C 2097152
#define OUT_U 6291456

#define SCAN_BLOCKS 2048
#define PREP_BASE   SCAN_BLOCKS
#define PREP_BLOCKS 256
#define COMB_BASE   (PREP_BASE + PREP_BLOCKS)      // 2304
#define COMB_BLOCKS 33
#define QB_BASE     (COMB_BASE + COMB_BLOCKS)      // 2337
#define QB_BLOCKS   (NC / 16)                      // 1024
#define PB_BASE     (QB_BASE + QB_BLOCKS)          // 3361
#define PB_BLOCKS   (NL / 16)                      // 512
#define MEGA_BLOCKS (PB_BASE + PB_BLOCKS)          // 3873

// ---------------- device scratch ----------------
__device__ float g_LT[(size_t)NL * BD];      // L_t node-major
__device__ float g_CnewT[(size_t)NC * BD];   // C_new node-major
__device__ float g_Q[(size_t)NC * BD];       // WCu1@C + bCu, node-major
__device__ float g_P[(size_t)NL * BD];       // WLu1@L + WLu3@Lflip + bLu, node-major
__device__ int   g_litCnt[NL];
__device__ int   g_litList[(size_t)NL * LCAP];
__device__ int   g_clauseCnt[NC];
__device__ int   g_clauseList[(size_t)NC * CCAP];
__device__ float g_Wcm[DD * DD];   // WCu2 @ WLmsg
__device__ float g_Wcl[DD * DD];   // WLu2 @ WCmsg
__device__ float g_bcm[DD];
__device__ float g_bcl[DD];
__device__ float g_sumL[BD];
__device__ float g_sumC[BD];

__device__ __forceinline__ float leaky(float x) { return x >= 0.f ? x : SLOPE * x; }

// acc2[8] (packed f32x2 pairs) += {w,w} * x[0..15]
#define FMA16P(acc2, wf, xptr) do {                                              \
    unsigned long long _w2;                                                      \
    asm("mov.b64 %0, {%1, %1};" : "=l"(_w2) : "f"(wf));                          \
    const ulonglong2* _x = (const ulonglong2*)(xptr);                            \
    ulonglong2 _p0 = _x[0]; ulonglong2 _p1 = _x[1];                              \
    ulonglong2 _p2 = _x[2]; ulonglong2 _p3 = _x[3];                              \
    asm("fma.rn.f32x2 %0, %1, %2, %0;" : "+l"(acc2[0]) : "l"(_w2), "l"(_p0.x));  \
    asm("fma.rn.f32x2 %0, %1, %2, %0;" : "+l"(acc2[1]) : "l"(_w2), "l"(_p0.y));  \
    asm("fma.rn.f32x2 %0, %1, %2, %0;" : "+l"(acc2[2]) : "l"(_w2), "l"(_p1.x));  \
    asm("fma.rn.f32x2 %0, %1, %2, %0;" : "+l"(acc2[3]) : "l"(_w2), "l"(_p1.y));  \
    asm("fma.rn.f32x2 %0, %1, %2, %0;" : "+l"(acc2[4]) : "l"(_w2), "l"(_p2.x));  \
    asm("fma.rn.f32x2 %0, %1, %2, %0;" : "+l"(acc2[5]) : "l"(_w2), "l"(_p2.y));  \
    asm("fma.rn.f32x2 %0, %1, %2, %0;" : "+l"(acc2[6]) : "l"(_w2), "l"(_p3.x));  \
    asm("fma.rn.f32x2 %0, %1, %2, %0;" : "+l"(acc2[7]) : "l"(_w2), "l"(_p3.y));  \
} while (0)

#define UNPACK16(acc, acc2)                                                       \
    _Pragma("unroll")                                                             \
    for (int _k = 0; _k < 8; _k++)                                                \
        asm("mov.b64 {%0, %1}, %2;" : "=f"(acc[2*_k]), "=f"(acc[2*_k+1]) : "l"(acc2[_k]));

// ---------------- kernels ----------------

__global__ void k_zero() {
    int i = blockIdx.x * blockDim.x + threadIdx.x;
    if (i < NL) g_litCnt[i] = 0;
    if (i < NC) g_clauseCnt[i] = 0;
    if (i < BD) { g_sumL[i] = 0.f; g_sumC[i] = 0.f; }
}

__device__ __forceinline__ void scan_add(int c, int l) {
    int p = atomicAdd(&g_clauseCnt[c], 1);
    if (p < CCAP) g_clauseList[(size_t)c * CCAP + p] = l;
    int q = atomicAdd(&g_litCnt[l], 1);
    if (q < LCAP) g_litList[(size_t)l * LCAP + q] = c;
}

__device__ __forceinline__ void scan_proc(uint4 v, unsigned idx) {
    if (v.x | v.y | v.z | v.w) {
        int c = idx >> 11;
        int lb = (idx & 2047) << 2;
        if (v.x) scan_add(c, lb);
        if (v.y) scan_add(c, lb + 1);
        if (v.z) scan_add(c, lb + 2);
        if (v.w) scan_add(c, lb + 3);
    }
}

// Heterogeneous: scan A | transpose L | combine msg weights | Q = WCu1@C+b | P = WLu1@L+WLu3@Lf+b
__global__ __launch_bounds__(256) void k_mega(const uint4* __restrict__ A4,
                                              const float* __restrict__ L,
                                              const float* __restrict__ C,
                                              const float* __restrict__ WCu,
                                              const float* __restrict__ WLmsg,
                                              const float* __restrict__ bLmsg,
                                              const float* __restrict__ WLu,
                                              const float* __restrict__ WCmsg,
                                              const float* __restrict__ bCmsg,
                                              const float* __restrict__ bCu,
                                              const float* __restrict__ bLu) {
    __shared__ float smem_buf[256 * 40 + 64];
    int bid = blockIdx.x;
    int tid = threadIdx.x;

    if (bid < SCAN_BLOCKS) {
        const unsigned stride = SCAN_BLOCKS * 256u;
        unsigned i = bid * 256u + tid;
        #pragma unroll 1
        for (int it = 0; it < 8; it++) {
            uint4 v0 = __ldcs(&A4[i]);
            uint4 v1 = __ldcs(&A4[i + stride]);
            uint4 v2 = __ldcs(&A4[i + 2 * stride]);
            uint4 v3 = __ldcs(&A4[i + 3 * stride]);
            uint4 v4 = __ldcs(&A4[i + 4 * stride]);
            uint4 v5 = __ldcs(&A4[i + 5 * stride]);
            uint4 v6 = __ldcs(&A4[i + 6 * stride]);
            uint4 v7 = __ldcs(&A4[i + 7 * stride]);
            unsigned any = (v0.x | v0.y | v0.z | v0.w) | (v1.x | v1.y | v1.z | v1.w)
                         | (v2.x | v2.y | v2.z | v2.w) | (v3.x | v3.y | v3.z | v3.w)
                         | (v4.x | v4.y | v4.z | v4.w) | (v5.x | v5.y | v5.z | v5.w)
                         | (v6.x | v6.y | v6.z | v6.w) | (v7.x | v7.y | v7.z | v7.w);
            if (any) {
                scan_proc(v0, i);
                scan_proc(v1, i + stride);
                scan_proc(v2, i + 2 * stride);
                scan_proc(v3, i + 3 * stride);
                scan_proc(v4, i + 4 * stride);
                scan_proc(v5, i + 5 * stride);
                scan_proc(v6, i + 6 * stride);
                scan_proc(v7, i + 7 * stride);
            }
            i += stride * 8;
        }
    } else if (bid < PREP_BASE + PREP_BLOCKS) {
        // transpose L_t [256][NL] -> g_LT [NL][256]
        float* s = smem_buf;   // 256*33
        int l0 = (bid - PREP_BASE) * 32;
        for (int idx = tid; idx < 256 * 32; idx += 256) {
            int r = idx >> 5, c = idx & 31;
            s[r * 33 + c] = L[(size_t)r * NL + l0 + c];
        }
        __syncthreads();
        #pragma unroll
        for (int li = 0; li < 32; li++)
            g_LT[(size_t)(l0 + li) * BD + tid] = s[tid * 33 + li];
    } else if (bid < COMB_BASE + COMB_BLOCKS) {
        int idx = (bid - COMB_BASE) * 256 + tid;
        if (idx < 4096) {
            int o = idx >> 6, i = idx & 63;
            float s = 0.f;
            #pragma unroll
            for (int j = 0; j < 64; j++) s += WCu[o * 128 + 64 + j] * WLmsg[j * 64 + i];
            g_Wcm[idx] = s;
        } else if (idx < 8192) {
            int k = idx - 4096;
            int o = k >> 6, i = k & 63;
            float s = 0.f;
            #pragma unroll
            for (int j = 0; j < 64; j++) s += WLu[o * 192 + 64 + j] * WCmsg[j * 64 + i];
            g_Wcl[k] = s;
        } else if (idx < 8256) {
            int o = idx - 8192;
            float s = 0.f;
            #pragma unroll
            for (int j = 0; j < 64; j++) s += WCu[o * 128 + 64 + j] * bLmsg[j];
            g_bcm[o] = s;
        } else if (idx < 8320) {
            int o = idx - 8256;
            float s = 0.f;
            #pragma unroll
            for (int j = 0; j < 64; j++) s += WLu[o * 192 + 64 + j] * bCmsg[j];
            g_bcl[o] = s;
        }
    } else if (bid < QB_BASE + QB_BLOCKS) {
        // Q tile: WCu1 @ C + bCu, 16 clauses
        float* s_ct = smem_buf;   // 256*20
        int c0 = (bid - QB_BASE) * 16;
        for (int idx = tid; idx < 256 * 16; idx += 256) {
            int r = idx >> 4, cc = idx & 15;
            s_ct[r * 20 + cc] = C[(size_t)r * NC + c0 + cc];
        }
        __syncthreads();
        int b = tid >> 6, ch = tid & 63;
        unsigned long long acc2[8];
        #pragma unroll
        for (int i = 0; i < 8; i++) acc2[i] = 0ull;
        const float4* w = (const float4*)(WCu + ch * 128);
        #pragma unroll 4
        for (int j4 = 0; j4 < 16; j4++) {
            float4 wv = __ldg(&w[j4]);
            const float* x = s_ct + (b * 64 + j4 * 4) * 20;
            FMA16P(acc2, wv.x, x);
            FMA16P(acc2, wv.y, x + 20);
            FMA16P(acc2, wv.z, x + 40);
            FMA16P(acc2, wv.w, x + 60);
        }
        float acc[16];
        UNPACK16(acc, acc2);
        float bb = __ldg(&bCu[ch]);
        #pragma unroll
        for (int cc = 0; cc < 16; cc++)
            g_Q[(size_t)(c0 + cc) * BD + tid] = acc[cc] + bb;
    } else {
        // P tile: WLu1 @ L + WLu3 @ L_flip + bLu, 16 literals
        float* s_X  = smem_buf;             // 256*20
        float* s_Xf = smem_buf + 256 * 20;  // 256*20
        int l0 = (bid - PB_BASE) * 16;
        int lf0 = (l0 + 4096) & (NL - 1);
        for (int idx = tid; idx < 256 * 16; idx += 256) {
            int r = idx >> 4, cc = idx & 15;
            s_X[r * 20 + cc]  = L[(size_t)r * NL + l0 + cc];
            s_Xf[r * 20 + cc] = L[(size_t)r * NL + lf0 + cc];
        }
        __syncthreads();
        int b = tid >> 6, ch = tid & 63;
        unsigned long long acc2[8];
        #pragma unroll
        for (int i = 0; i < 8; i++) acc2[i] = 0ull;
        const float4* w1 = (const float4*)(WLu + ch * 192);
        const float4* w3 = (const float4*)(WLu + ch * 192 + 128);
        #pragma unroll 4
        for (int j4 = 0; j4 < 16; j4++) {
            float4 wv = __ldg(&w1[j4]);
            const float* x = s_X + (b * 64 + j4 * 4) * 20;
            FMA16P(acc2, wv.x, x);
            FMA16P(acc2, wv.y, x + 20);
            FMA16P(acc2, wv.z, x + 40);
            FMA16P(acc2, wv.w, x + 60);
        }
        #pragma unroll 4
        for (int j4 = 0; j4 < 16; j4++) {
            float4 wv = __ldg(&w3[j4]);
            const float* x = s_Xf + (b * 64 + j4 * 4) * 20;
            FMA16P(acc2, wv.x, x);
            FMA16P(acc2, wv.y, x + 20);
            FMA16P(acc2, wv.z, x + 40);
            FMA16P(acc2, wv.w, x + 60);
        }
        float acc[16];
        UNPACK16(acc, acc2);
        float bb = __ldg(&bLu[ch]);
        #pragma unroll
        for (int cc = 0; cc < 16; cc++)
            g_P[(size_t)(l0 + cc) * BD + tid] = acc[cc] + bb;
    }
}

// Clause update: gather + message matvec only; add precomputed Q.
__global__ __launch_bounds__(256) void k_clauseUp(float* __restrict__ outC) {
    extern __shared__ float sm[];
    float* s_S   = sm;                     // 256*20
    int*   s_cnt = (int*)(s_S + 256 * 20); // 16
    int*   s_list = s_cnt + 16;            // 16*SCAPC

    int tid = threadIdx.x;
    int c0 = blockIdx.x * 16;

    if (tid < 16) s_cnt[tid] = min(g_clauseCnt[c0 + tid], SCAPC);
    __syncthreads();
    for (int idx = tid; idx < 16 * SCAPC; idx += 256) {
        int cc = idx / SCAPC, i = idx - cc * SCAPC;
        if (i < s_cnt[cc]) s_list[idx] = g_clauseList[(size_t)(c0 + cc) * CCAP + i];
    }
    __syncthreads();

    #pragma unroll 1
    for (int cc = 0; cc < 16; cc++) {
        int cnt = s_cnt[cc];
        const int* lst = s_list + cc * SCAPC;
        float m0 = 0.f, m1 = 0.f, m2 = 0.f, m3 = 0.f;
        float m4 = 0.f, m5 = 0.f, m6 = 0.f, m7 = 0.f;
        int i = 0;
        for (; i + 7 < cnt; i += 8) {
            m0 += __ldg(&g_LT[(size_t)lst[i]     * BD + tid]);
            m1 += __ldg(&g_LT[(size_t)lst[i + 1] * BD + tid]);
            m2 += __ldg(&g_LT[(size_t)lst[i + 2] * BD + tid]);
            m3 += __ldg(&g_LT[(size_t)lst[i + 3] * BD + tid]);
            m4 += __ldg(&g_LT[(size_t)lst[i + 4] * BD + tid]);
            m5 += __ldg(&g_LT[(size_t)lst[i + 5] * BD + tid]);
            m6 += __ldg(&g_LT[(size_t)lst[i + 6] * BD + tid]);
            m7 += __ldg(&g_LT[(size_t)lst[i + 7] * BD + tid]);
        }
        for (; i < cnt; i++) m0 += __ldg(&g_LT[(size_t)lst[i] * BD + tid]);
        s_S[tid * 20 + cc] = ((m0 + m1) + (m2 + m3)) + ((m4 + m5) + (m6 + m7));
    }
    __syncthreads();

    int b = tid >> 6, ch = tid & 63;
    unsigned long long acc2[8];
    #pragma unroll
    for (int i = 0; i < 8; i++) acc2[i] = 0ull;
    const float4* wc = (const float4*)(g_Wcm + ch * 64);
    #pragma unroll 4
    for (int j4 = 0; j4 < 16; j4++) {
        float4 wv = __ldg(&wc[j4]);
        const float* x = s_S + (b * 64 + j4 * 4) * 20;
        FMA16P(acc2, wv.x, x);
        FMA16P(acc2, wv.y, x + 20);
        FMA16P(acc2, wv.z, x + 40);
        FMA16P(acc2, wv.w, x + 60);
    }
    float acc[16];
    UNPACK16(acc, acc2);

    float bc = __ldg(&g_bcm[ch]);
    float lsum = 0.f;
    #pragma unroll
    for (int cc = 0; cc < 16; cc++) {
        float q = __ldg(&g_Q[(size_t)(c0 + cc) * BD + tid]);
        float v = leaky(acc[cc] + q + (float)s_cnt[cc] * bc);
        acc[cc] = v;
        lsum += v;
        g_CnewT[(size_t)(c0 + cc) * BD + tid] = v;
    }
    float4* orow = (float4*)(outC + (size_t)tid * NC + c0);
    orow[0] = make_float4(acc[0], acc[1], acc[2], acc[3]);
    orow[1] = make_float4(acc[4], acc[5], acc[6], acc[7]);
    orow[2] = make_float4(acc[8], acc[9], acc[10], acc[11]);
    orow[3] = make_float4(acc[12], acc[13], acc[14], acc[15]);
    atomicAdd(&g_sumC[tid], lsum);
}

// Literal update: gather + message matvec only; add precomputed P.
__global__ __launch_bounds__(256) void k_literalUp(float* __restrict__ outL) {
    extern __shared__ float sm[];
    float* s_S   = sm;                     // 256*20
    int*   s_cnt = (int*)(s_S + 256 * 20); // 16
    int*   s_list = s_cnt + 16;            // 16*LCAP

    int tid = threadIdx.x;
    int l0 = blockIdx.x * 16;

    if (tid < 16) s_cnt[tid] = min(g_litCnt[l0 + tid], LCAP);
    __syncthreads();
    for (int idx = tid; idx < 16 * LCAP; idx += 256) {
        int cc = idx >> 6, i = idx & 63;
        if (i < s_cnt[cc]) s_list[idx] = g_litList[(size_t)(l0 + cc) * LCAP + i];
    }
    __syncthreads();

    #pragma unroll 1
    for (int cc = 0; cc < 16; cc++) {
        int cnt = s_cnt[cc];
        const int* lst = s_list + cc * LCAP;
        float m0 = 0.f, m1 = 0.f, m2 = 0.f, m3 = 0.f;
        float m4 = 0.f, m5 = 0.f, m6 = 0.f, m7 = 0.f;
        int i = 0;
        for (; i + 7 < cnt; i += 8) {
            m0 += __ldg(&g_CnewT[(size_t)lst[i]     * BD + tid]);
            m1 += __ldg(&g_CnewT[(size_t)lst[i + 1] * BD + tid]);
            m2 += __ldg(&g_CnewT[(size_t)lst[i + 2] * BD + tid]);
            m3 += __ldg(&g_CnewT[(size_t)lst[i + 3] * BD + tid]);
            m4 += __ldg(&g_CnewT[(size_t)lst[i + 4] * BD + tid]);
            m5 += __ldg(&g_CnewT[(size_t)lst[i + 5] * BD + tid]);
            m6 += __ldg(&g_CnewT[(size_t)lst[i + 6] * BD + tid]);
            m7 += __ldg(&g_CnewT[(size_t)lst[i + 7] * BD + tid]);
        }
        for (; i < cnt; i++) m0 += __ldg(&g_CnewT[(size_t)lst[i] * BD + tid]);
        s_S[tid * 20 + cc] = ((m0 + m1) + (m2 + m3)) + ((m4 + m5) + (m6 + m7));
    }
    __syncthreads();

    int b = tid >> 6, ch = tid & 63;
    unsigned long long acc2[8];
    #pragma unroll
    for (int i = 0; i < 8; i++) acc2[i] = 0ull;
    const float4* wl = (const float4*)(g_Wcl + ch * 64);
    #pragma unroll 4
    for (int j4 = 0; j4 < 16; j4++) {
        float4 wv = __ldg(&wl[j4]);
        const float* x = s_S + (b * 64 + j4 * 4) * 20;
        FMA16P(acc2, wv.x, x);
        FMA16P(acc2, wv.y, x + 20);
        FMA16P(acc2, wv.z, x + 40);
        FMA16P(acc2, wv.w, x + 60);
    }
    float acc[16];
    UNPACK16(acc, acc2);

    float bc = __ldg(&g_bcl[ch]);
    float lsum = 0.f;
    #pragma unroll
    for (int cc = 0; cc < 16; cc++) {
        float p = __ldg(&g_P[(size_t)(l0 + cc) * BD + tid]);
        float v = leaky(acc[cc] + p + (float)s_cnt[cc] * bc);
        acc[cc] = v;
        lsum += v;
    }
    float4* orow = (float4*)(outL + (size_t)tid * NL + l0);
    orow[0] = make_float4(acc[0], acc[1], acc[2], acc[3]);
    orow[1] = make_float4(acc[4], acc[5], acc[6], acc[7]);
    orow[2] = make_float4(acc[8], acc[9], acc[10], acc[11]);
    orow[3] = make_float4(acc[12], acc[13], acc[14], acc[15]);
    atomicAdd(&g_sumL[tid], lsum);
}

__global__ void k_U(const float* __restrict__ U, const float* __restrict__ WUu,
                    const float* __restrict__ bUu, float* __restrict__ out) {
    __shared__ float glb[4 * 192];
    int tid = threadIdx.x;
    int b = tid >> 6, ch = tid & 63;
    glb[b * 192 + ch]       = g_sumL[tid];
    glb[b * 192 + 64 + ch]  = g_sumC[tid];
    glb[b * 192 + 128 + ch] = U[tid];
    __syncthreads();
    float s = bUu[ch];
    #pragma unroll 8
    for (int i = 0; i < 192; i++) s += WUu[ch * 192 + i] * glb[b * 192 + i];
    out[tid] = leaky(s);
}

// ---------------- launch ----------------
extern "C" void kernel_launch(void* const* d_in, const int* in_sizes, int n_in,
                              void* d_out, int out_size) {
    const float* L     = (const float*)d_in[0];
    const float* C     = (const float*)d_in[1];
    const float* U     = (const float*)d_in[2];
    const float* A     = (const float*)d_in[3];
    const float* WLmsg = (const float*)d_in[5];
    const float* bLmsg = (const float*)d_in[6];
    const float* WCmsg = (const float*)d_in[7];
    const float* bCmsg = (const float*)d_in[8];
    const float* WLu   = (const float*)d_in[9];
    const float* bLu   = (const float*)d_in[10];
    const float* WCu   = (const float*)d_in[11];
    const float* bCu   = (const float*)d_in[12];
    const float* WUu   = (const float*)d_in[13];
    const float* bUu   = (const float*)d_in[14];
    float* out = (float*)d_out;

    const int smem_clause  = (256 * 20 + 16 + 16 * SCAPC) * 4;
    const int smem_literal = (256 * 20 + 16 + 16 * LCAP) * 4;
    cudaFuncSetAttribute(k_clauseUp,  cudaFuncAttributeMaxDynamicSharedMemorySize, smem_clause);
    cudaFuncSetAttribute(k_literalUp, cudaFuncAttributeMaxDynamicSharedMemorySize, smem_literal);

    k_zero<<<64, 256>>>();
    k_mega<<<MEGA_BLOCKS, 256>>>((const uint4*)A, L, C, WCu, WLmsg, bLmsg,
                                 WLu, WCmsg, bCmsg, bCu, bLu);
    k_clauseUp<<<NC / 16, 256, smem_clause>>>(out + OUT_C);
    k_literalUp<<<NL / 16, 256, smem_literal>>>(out + OUT_L);
    k_U<<<1, 256>>>(U, WUu, bUu, out + OUT_U);
}

// round 12
// speedup vs baseline: 1.3569x; 1.0672x over previous
#include <cuda_runtime.h>

#define NL 8192
#define NC 16384
#define BD 256
#define DD 64
#define SLOPE 0.01f
#define LCAP 64
#define CCAP 64
#define SCAPC 40

#define OUT_L 0
#define OUT_C 2097152
#define OUT_U 6291456

#define SCAN_BLOCKS 2048
#define PREP_BLOCKS 256
#define COMB_BLOCKS 33
#define QB_BLOCKS   (NC / 16)                      // 1024
#define PB_BLOCKS   (NL / 16)                      // 512
#define OTHER_BLOCKS (PREP_BLOCKS + COMB_BLOCKS + QB_BLOCKS + PB_BLOCKS)  // 1825
#define MEGA_BLOCKS (SCAN_BLOCKS + OTHER_BLOCKS)   // 3873

// ---------------- device scratch ----------------
__device__ float g_LT[(size_t)NL * BD];      // L_t node-major
__device__ float g_CnewT[(size_t)NC * BD];   // C_new node-major
__device__ float g_Q[(size_t)NC * BD];       // WCu1@C + bCu, node-major
__device__ float g_P[(size_t)NL * BD];       // WLu1@L + WLu3@Lflip + bLu, node-major
__device__ int   g_litCnt[NL];
__device__ int   g_litList[(size_t)NL * LCAP];
__device__ int   g_clauseCnt[NC];
__device__ int   g_clauseList[(size_t)NC * CCAP];
__device__ float g_Wcm[DD * DD];   // WCu2 @ WLmsg
__device__ float g_Wcl[DD * DD];   // WLu2 @ WCmsg
__device__ float g_bcm[DD];
__device__ float g_bcl[DD];
__device__ float g_sumL[BD];
__device__ float g_sumC[BD];

__device__ __forceinline__ float leaky(float x) { return x >= 0.f ? x : SLOPE * x; }

// acc2[8] (packed f32x2 pairs) += {w,w} * x[0..15]
#define FMA16P(acc2, wf, xptr) do {                                              \
    unsigned long long _w2;                                                      \
    asm("mov.b64 %0, {%1, %1};" : "=l"(_w2) : "f"(wf));                          \
    const ulonglong2* _x = (const ulonglong2*)(xptr);                            \
    ulonglong2 _p0 = _x[0]; ulonglong2 _p1 = _x[1];                              \
    ulonglong2 _p2 = _x[2]; ulonglong2 _p3 = _x[3];                              \
    asm("fma.rn.f32x2 %0, %1, %2, %0;" : "+l"(acc2[0]) : "l"(_w2), "l"(_p0.x));  \
    asm("fma.rn.f32x2 %0, %1, %2, %0;" : "+l"(acc2[1]) : "l"(_w2), "l"(_p0.y));  \
    asm("fma.rn.f32x2 %0, %1, %2, %0;" : "+l"(acc2[2]) : "l"(_w2), "l"(_p1.x));  \
    asm("fma.rn.f32x2 %0, %1, %2, %0;" : "+l"(acc2[3]) : "l"(_w2), "l"(_p1.y));  \
    asm("fma.rn.f32x2 %0, %1, %2, %0;" : "+l"(acc2[4]) : "l"(_w2), "l"(_p2.x));  \
    asm("fma.rn.f32x2 %0, %1, %2, %0;" : "+l"(acc2[5]) : "l"(_w2), "l"(_p2.y));  \
    asm("fma.rn.f32x2 %0, %1, %2, %0;" : "+l"(acc2[6]) : "l"(_w2), "l"(_p3.x));  \
    asm("fma.rn.f32x2 %0, %1, %2, %0;" : "+l"(acc2[7]) : "l"(_w2), "l"(_p3.y));  \
} while (0)

#define UNPACK16(acc, acc2)                                                       \
    _Pragma("unroll")                                                             \
    for (int _k = 0; _k < 8; _k++)                                                \
        asm("mov.b64 {%0, %1}, %2;" : "=f"(acc[2*_k]), "=f"(acc[2*_k+1]) : "l"(acc2[_k]));

// ---------------- kernels ----------------

__global__ void k_zero() {
    int i = blockIdx.x * blockDim.x + threadIdx.x;
    if (i < NL) g_litCnt[i] = 0;
    if (i < NC) g_clauseCnt[i] = 0;
    if (i < BD) { g_sumL[i] = 0.f; g_sumC[i] = 0.f; }
}

__device__ __forceinline__ void scan_add(int c, int l) {
    int p = atomicAdd(&g_clauseCnt[c], 1);
    if (p < CCAP) g_clauseList[(size_t)c * CCAP + p] = l;
    int q = atomicAdd(&g_litCnt[l], 1);
    if (q < LCAP) g_litList[(size_t)l * LCAP + q] = c;
}

__device__ __forceinline__ void scan_proc(uint4 v, unsigned idx) {
    if (v.x | v.y | v.z | v.w) {
        int c = idx >> 11;
        int lb = (idx & 2047) << 2;
        if (v.x) scan_add(c, lb);
        if (v.y) scan_add(c, lb + 1);
        if (v.z) scan_add(c, lb + 2);
        if (v.w) scan_add(c, lb + 3);
    }
}

// Heterogeneous mega-kernel with Bresenham-interleaved roles so DRAM-bound scan
// blocks and FMA-bound Q/P blocks co-reside in every scheduling wave.
__global__ __launch_bounds__(256) void k_mega(const uint4* __restrict__ A4,
                                              const float* __restrict__ L,
                                              const float* __restrict__ C,
                                              const float* __restrict__ WCu,
                                              const float* __restrict__ WLmsg,
                                              const float* __restrict__ bLmsg,
                                              const float* __restrict__ WLu,
                                              const float* __restrict__ WCmsg,
                                              const float* __restrict__ bCmsg,
                                              const float* __restrict__ bCu,
                                              const float* __restrict__ bLu) {
    __shared__ float smem_buf[256 * 40 + 64];
    int bid = blockIdx.x;
    int tid = threadIdx.x;

    // Bresenham role interleave: scan iff floor((bid+1)*S/T) > floor(bid*S/T)
    int s_lo = (int)(((long long)bid * SCAN_BLOCKS) / MEGA_BLOCKS);
    int s_hi = (int)(((long long)(bid + 1) * SCAN_BLOCKS) / MEGA_BLOCKS);
    bool is_scan = (s_hi > s_lo);
    int scan_id = s_lo;
    int other_id = bid - s_lo;   // count of non-scan blocks before bid

    if (is_scan) {
        const unsigned stride = SCAN_BLOCKS * 256u;
        unsigned i = scan_id * 256u + tid;
        #pragma unroll 1
        for (int it = 0; it < 8; it++) {
            uint4 v0 = __ldcs(&A4[i]);
            uint4 v1 = __ldcs(&A4[i + stride]);
            uint4 v2 = __ldcs(&A4[i + 2 * stride]);
            uint4 v3 = __ldcs(&A4[i + 3 * stride]);
            uint4 v4 = __ldcs(&A4[i + 4 * stride]);
            uint4 v5 = __ldcs(&A4[i + 5 * stride]);
            uint4 v6 = __ldcs(&A4[i + 6 * stride]);
            uint4 v7 = __ldcs(&A4[i + 7 * stride]);
            unsigned any = (v0.x | v0.y | v0.z | v0.w) | (v1.x | v1.y | v1.z | v1.w)
                         | (v2.x | v2.y | v2.z | v2.w) | (v3.x | v3.y | v3.z | v3.w)
                         | (v4.x | v4.y | v4.z | v4.w) | (v5.x | v5.y | v5.z | v5.w)
                         | (v6.x | v6.y | v6.z | v6.w) | (v7.x | v7.y | v7.z | v7.w);
            if (any) {
                scan_proc(v0, i);
                scan_proc(v1, i + stride);
                scan_proc(v2, i + 2 * stride);
                scan_proc(v3, i + 3 * stride);
                scan_proc(v4, i + 4 * stride);
                scan_proc(v5, i + 5 * stride);
                scan_proc(v6, i + 6 * stride);
                scan_proc(v7, i + 7 * stride);
            }
            i += stride * 8;
        }
    } else if (other_id < PREP_BLOCKS) {
        // transpose L_t [256][NL] -> g_LT [NL][256]
        float* s = smem_buf;   // 256*33
        int l0 = other_id * 32;
        for (int idx = tid; idx < 256 * 32; idx += 256) {
            int r = idx >> 5, c = idx & 31;
            s[r * 33 + c] = L[(size_t)r * NL + l0 + c];
        }
        __syncthreads();
        #pragma unroll
        for (int li = 0; li < 32; li++)
            g_LT[(size_t)(l0 + li) * BD + tid] = s[tid * 33 + li];
    } else if (other_id < PREP_BLOCKS + COMB_BLOCKS) {
        int idx = (other_id - PREP_BLOCKS) * 256 + tid;
        if (idx < 4096) {
            int o = idx >> 6, i = idx & 63;
            float s = 0.f;
            #pragma unroll
            for (int j = 0; j < 64; j++) s += WCu[o * 128 + 64 + j] * WLmsg[j * 64 + i];
            g_Wcm[idx] = s;
        } else if (idx < 8192) {
            int k = idx - 4096;
            int o = k >> 6, i = k & 63;
            float s = 0.f;
            #pragma unroll
            for (int j = 0; j < 64; j++) s += WLu[o * 192 + 64 + j] * WCmsg[j * 64 + i];
            g_Wcl[k] = s;
        } else if (idx < 8256) {
            int o = idx - 8192;
            float s = 0.f;
            #pragma unroll
            for (int j = 0; j < 64; j++) s += WCu[o * 128 + 64 + j] * bLmsg[j];
            g_bcm[o] = s;
        } else if (idx < 8320) {
            int o = idx - 8256;
            float s = 0.f;
            #pragma unroll
            for (int j = 0; j < 64; j++) s += WLu[o * 192 + 64 + j] * bCmsg[j];
            g_bcl[o] = s;
        }
    } else if (other_id < PREP_BLOCKS + COMB_BLOCKS + QB_BLOCKS) {
        // Q tile: WCu1 @ C + bCu, 16 clauses
        float* s_ct = smem_buf;   // 256*20
        int c0 = (other_id - PREP_BLOCKS - COMB_BLOCKS) * 16;
        for (int idx = tid; idx < 256 * 16; idx += 256) {
            int r = idx >> 4, cc = idx & 15;
            s_ct[r * 20 + cc] = C[(size_t)r * NC + c0 + cc];
        }
        __syncthreads();
        int b = tid >> 6, ch = tid & 63;
        unsigned long long acc2[8];
        #pragma unroll
        for (int i = 0; i < 8; i++) acc2[i] = 0ull;
        const float4* w = (const float4*)(WCu + ch * 128);
        #pragma unroll 4
        for (int j4 = 0; j4 < 16; j4++) {
            float4 wv = __ldg(&w[j4]);
            const float* x = s_ct + (b * 64 + j4 * 4) * 20;
            FMA16P(acc2, wv.x, x);
            FMA16P(acc2, wv.y, x + 20);
            FMA16P(acc2, wv.z, x + 40);
            FMA16P(acc2, wv.w, x + 60);
        }
        float acc[16];
        UNPACK16(acc, acc2);
        float bb = __ldg(&bCu[ch]);
        #pragma unroll
        for (int cc = 0; cc < 16; cc++)
            g_Q[(size_t)(c0 + cc) * BD + tid] = acc[cc] + bb;
    } else {
        // P tile: WLu1 @ L + WLu3 @ L_flip + bLu, 16 literals
        float* s_X  = smem_buf;             // 256*20
        float* s_Xf = smem_buf + 256 * 20;  // 256*20
        int l0 = (other_id - PREP_BLOCKS - COMB_BLOCKS - QB_BLOCKS) * 16;
        int lf0 = (l0 + 4096) & (NL - 1);
        for (int idx = tid; idx < 256 * 16; idx += 256) {
            int r = idx >> 4, cc = idx & 15;
            s_X[r * 20 + cc]  = L[(size_t)r * NL + l0 + cc];
            s_Xf[r * 20 + cc] = L[(size_t)r * NL + lf0 + cc];
        }
        __syncthreads();
        int b = tid >> 6, ch = tid & 63;
        unsigned long long acc2[8];
        #pragma unroll
        for (int i = 0; i < 8; i++) acc2[i] = 0ull;
        const float4* w1 = (const float4*)(WLu + ch * 192);
        const float4* w3 = (const float4*)(WLu + ch * 192 + 128);
        #pragma unroll 4
        for (int j4 = 0; j4 < 16; j4++) {
            float4 wv = __ldg(&w1[j4]);
            const float* x = s_X + (b * 64 + j4 * 4) * 20;
            FMA16P(acc2, wv.x, x);
            FMA16P(acc2, wv.y, x + 20);
            FMA16P(acc2, wv.z, x + 40);
            FMA16P(acc2, wv.w, x + 60);
        }
        #pragma unroll 4
        for (int j4 = 0; j4 < 16; j4++) {
            float4 wv = __ldg(&w3[j4]);
            const float* x = s_Xf + (b * 64 + j4 * 4) * 20;
            FMA16P(acc2, wv.x, x);
            FMA16P(acc2, wv.y, x + 20);
            FMA16P(acc2, wv.z, x + 40);
            FMA16P(acc2, wv.w, x + 60);
        }
        float acc[16];
        UNPACK16(acc, acc2);
        float bb = __ldg(&bLu[ch]);
        #pragma unroll
        for (int cc = 0; cc < 16; cc++)
            g_P[(size_t)(l0 + cc) * BD + tid] = acc[cc] + bb;
    }
}

// Clause update: gather + message matvec only; add precomputed Q.
__global__ __launch_bounds__(256) void k_clauseUp(float* __restrict__ outC) {
    extern __shared__ float sm[];
    float* s_S   = sm;                     // 256*20
    int*   s_cnt = (int*)(s_S + 256 * 20); // 16
    int*   s_list = s_cnt + 16;            // 16*SCAPC

    int tid = threadIdx.x;
    int c0 = blockIdx.x * 16;

    if (tid < 16) s_cnt[tid] = min(g_clauseCnt[c0 + tid], SCAPC);
    __syncthreads();
    for (int idx = tid; idx < 16 * SCAPC; idx += 256) {
        int cc = idx / SCAPC, i = idx - cc * SCAPC;
        if (i < s_cnt[cc]) s_list[idx] = g_clauseList[(size_t)(c0 + cc) * CCAP + i];
    }
    __syncthreads();

    #pragma unroll 1
    for (int cc = 0; cc < 16; cc++) {
        int cnt = s_cnt[cc];
        const int* lst = s_list + cc * SCAPC;
        float m0 = 0.f, m1 = 0.f, m2 = 0.f, m3 = 0.f;
        float m4 = 0.f, m5 = 0.f, m6 = 0.f, m7 = 0.f;
        int i = 0;
        for (; i + 7 < cnt; i += 8) {
            m0 += __ldg(&g_LT[(size_t)lst[i]     * BD + tid]);
            m1 += __ldg(&g_LT[(size_t)lst[i + 1] * BD + tid]);
            m2 += __ldg(&g_LT[(size_t)lst[i + 2] * BD + tid]);
            m3 += __ldg(&g_LT[(size_t)lst[i + 3] * BD + tid]);
            m4 += __ldg(&g_LT[(size_t)lst[i + 4] * BD + tid]);
            m5 += __ldg(&g_LT[(size_t)lst[i + 5] * BD + tid]);
            m6 += __ldg(&g_LT[(size_t)lst[i + 6] * BD + tid]);
            m7 += __ldg(&g_LT[(size_t)lst[i + 7] * BD + tid]);
        }
        for (; i < cnt; i++) m0 += __ldg(&g_LT[(size_t)lst[i] * BD + tid]);
        s_S[tid * 20 + cc] = ((m0 + m1) + (m2 + m3)) + ((m4 + m5) + (m6 + m7));
    }
    __syncthreads();

    int b = tid >> 6, ch = tid & 63;
    unsigned long long acc2[8];
    #pragma unroll
    for (int i = 0; i < 8; i++) acc2[i] = 0ull;
    const float4* wc = (const float4*)(g_Wcm + ch * 64);
    #pragma unroll 4
    for (int j4 = 0; j4 < 16; j4++) {
        float4 wv = __ldg(&wc[j4]);
        const float* x = s_S + (b * 64 + j4 * 4) * 20;
        FMA16P(acc2, wv.x, x);
        FMA16P(acc2, wv.y, x + 20);
        FMA16P(acc2, wv.z, x + 40);
        FMA16P(acc2, wv.w, x + 60);
    }
    float acc[16];
    UNPACK16(acc, acc2);

    float bc = __ldg(&g_bcm[ch]);
    float lsum = 0.f;
    #pragma unroll
    for (int cc = 0; cc < 16; cc++) {
        float q = __ldg(&g_Q[(size_t)(c0 + cc) * BD + tid]);
        float v = leaky(acc[cc] + q + (float)s_cnt[cc] * bc);
        acc[cc] = v;
        lsum += v;
        g_CnewT[(size_t)(c0 + cc) * BD + tid] = v;
    }
    float4* orow = (float4*)(outC + (size_t)tid * NC + c0);
    orow[0] = make_float4(acc[0], acc[1], acc[2], acc[3]);
    orow[1] = make_float4(acc[4], acc[5], acc[6], acc[7]);
    orow[2] = make_float4(acc[8], acc[9], acc[10], acc[11]);
    orow[3] = make_float4(acc[12], acc[13], acc[14], acc[15]);
    atomicAdd(&g_sumC[tid], lsum);
}

// Literal update: gather + message matvec only; add precomputed P.
__global__ __launch_bounds__(256) void k_literalUp(float* __restrict__ outL) {
    extern __shared__ float sm[];
    float* s_S   = sm;                     // 256*20
    int*   s_cnt = (int*)(s_S + 256 * 20); // 16
    int*   s_list = s_cnt + 16;            // 16*LCAP

    int tid = threadIdx.x;
    int l0 = blockIdx.x * 16;

    if (tid < 16) s_cnt[tid] = min(g_litCnt[l0 + tid], LCAP);
    __syncthreads();
    for (int idx = tid; idx < 16 * LCAP; idx += 256) {
        int cc = idx >> 6, i = idx & 63;
        if (i < s_cnt[cc]) s_list[idx] = g_litList[(size_t)(l0 + cc) * LCAP + i];
    }
    __syncthreads();

    #pragma unroll 1
    for (int cc = 0; cc < 16; cc++) {
        int cnt = s_cnt[cc];
        const int* lst = s_list + cc * LCAP;
        float m0 = 0.f, m1 = 0.f, m2 = 0.f, m3 = 0.f;
        float m4 = 0.f, m5 = 0.f, m6 = 0.f, m7 = 0.f;
        int i = 0;
        for (; i + 7 < cnt; i += 8) {
            m0 += __ldg(&g_CnewT[(size_t)lst[i]     * BD + tid]);
            m1 += __ldg(&g_CnewT[(size_t)lst[i + 1] * BD + tid]);
            m2 += __ldg(&g_CnewT[(size_t)lst[i + 2] * BD + tid]);
            m3 += __ldg(&g_CnewT[(size_t)lst[i + 3] * BD + tid]);
            m4 += __ldg(&g_CnewT[(size_t)lst[i + 4] * BD + tid]);
            m5 += __ldg(&g_CnewT[(size_t)lst[i + 5] * BD + tid]);
            m6 += __ldg(&g_CnewT[(size_t)lst[i + 6] * BD + tid]);
            m7 += __ldg(&g_CnewT[(size_t)lst[i + 7] * BD + tid]);
        }
        for (; i < cnt; i++) m0 += __ldg(&g_CnewT[(size_t)lst[i] * BD + tid]);
        s_S[tid * 20 + cc] = ((m0 + m1) + (m2 + m3)) + ((m4 + m5) + (m6 + m7));
    }
    __syncthreads();

    int b = tid >> 6, ch = tid & 63;
    unsigned long long acc2[8];
    #pragma unroll
    for (int i = 0; i < 8; i++) acc2[i] = 0ull;
    const float4* wl = (const float4*)(g_Wcl + ch * 64);
    #pragma unroll 4
    for (int j4 = 0; j4 < 16; j4++) {
        float4 wv = __ldg(&wl[j4]);
        const float* x = s_S + (b * 64 + j4 * 4) * 20;
        FMA16P(acc2, wv.x, x);
        FMA16P(acc2, wv.y, x + 20);
        FMA16P(acc2, wv.z, x + 40);
        FMA16P(acc2, wv.w, x + 60);
    }
    float acc[16];
    UNPACK16(acc, acc2);

    float bc = __ldg(&g_bcl[ch]);
    float lsum = 0.f;
    #pragma unroll
    for (int cc = 0; cc < 16; cc++) {
        float p = __ldg(&g_P[(size_t)(l0 + cc) * BD + tid]);
        float v = leaky(acc[cc] + p + (float)s_cnt[cc] * bc);
        acc[cc] = v;
        lsum += v;
    }
    float4* orow = (float4*)(outL + (size_t)tid * NL + l0);
    orow[0] = make_float4(acc[0], acc[1], acc[2], acc[3]);
    orow[1] = make_float4(acc[4], acc[5], acc[6], acc[7]);
    orow[2] = make_float4(acc[8], acc[9], acc[10], acc[11]);
    orow[3] = make_float4(acc[12], acc[13], acc[14], acc[15]);
    atomicAdd(&g_sumL[tid], lsum);
}

__global__ void k_U(const float* __restrict__ U, const float* __restrict__ WUu,
                    const float* __restrict__ bUu, float* __restrict__ out) {
    __shared__ float glb[4 * 192];
    int tid = threadIdx.x;
    int b = tid >> 6, ch = tid & 63;
    glb[b * 192 + ch]       = g_sumL[tid];
    glb[b * 192 + 64 + ch]  = g_sumC[tid];
    glb[b * 192 + 128 + ch] = U[tid];
    __syncthreads();
    float s = bUu[ch];
    #pragma unroll 8
    for (int i = 0; i < 192; i++) s += WUu[ch * 192 + i] * glb[b * 192 + i];
    out[tid] = leaky(s);
}

// ---------------- launch ----------------
extern "C" void kernel_launch(void* const* d_in, const int* in_sizes, int n_in,
                              void* d_out, int out_size) {
    const float* L     = (const float*)d_in[0];
    const float* C     = (const float*)d_in[1];
    const float* U     = (const float*)d_in[2];
    const float* A     = (const float*)d_in[3];
    const float* WLmsg = (const float*)d_in[5];
    const float* bLmsg = (const float*)d_in[6];
    const float* WCmsg = (const float*)d_in[7];
    const float* bCmsg = (const float*)d_in[8];
    const float* WLu   = (const float*)d_in[9];
    const float* bLu   = (const float*)d_in[10];
    const float* WCu   = (const float*)d_in[11];
    const float* bCu   = (const float*)d_in[12];
    const float* WUu   = (const float*)d_in[13];
    const float* bUu   = (const float*)d_in[14];
    float* out = (float*)d_out;

    const int smem_clause  = (256 * 20 + 16 + 16 * SCAPC) * 4;
    const int smem_literal = (256 * 20 + 16 + 16 * LCAP) * 4;
    cudaFuncSetAttribute(k_clauseUp,  cudaFuncAttributeMaxDynamicSharedMemorySize, smem_clause);
    cudaFuncSetAttribute(k_literalUp, cudaFuncAttributeMaxDynamicSharedMemorySize, smem_literal);

    k_zero<<<64, 256>>>();
    k_mega<<<MEGA_BLOCKS, 256>>>((const uint4*)A, L, C, WCu, WLmsg, bLmsg,
                                 WLu, WCmsg, bCmsg, bCu, bLu);
    k_clauseUp<<<NC / 16, 256, smem_clause>>>(out + OUT_C);
    k_literalUp<<<NL / 16, 256, smem_literal>>>(out + OUT_L);
    k_U<<<1, 256>>>(U, WUu, bUu, out + OUT_U);
}